// round 15
// baseline (speedup 1.0000x reference)
#include <cuda_runtime.h>
#include <cstdint>

#define BATCH 8
#define CH    512
#define PIX   4096            // 64*64
#define CP    (CH*PIX)        // 2,097,152
#define TOT   (BATCH*CP)      // 16,777,216

// Scratch (device globals: allocation-free per harness rules)
__device__ float  g_f[2][TOT];      // conv outputs f_opt / f_sar
__device__ float  g_S[2][TOT];      // Gram matrices S_opt / S_sar
__device__ float4 g_red[BATCH*PIX]; // per-(b,pixel): (m1, z1, m2, z2)

// ---------------------------------------------------------------------------
// tf32 helpers
// ---------------------------------------------------------------------------
__device__ __forceinline__ float tf32r(float x) {
    uint32_t u; asm("cvt.rna.tf32.f32 %0, %1;" : "=r"(u) : "f"(x));
    return __uint_as_float(u);
}
__device__ __forceinline__ void mma1688(float* c, const uint32_t* a, const uint32_t* b) {
    asm volatile(
        "mma.sync.aligned.m16n8k8.row.col.f32.tf32.tf32.f32 "
        "{%0,%1,%2,%3}, {%4,%5,%6,%7}, {%8,%9}, {%0,%1,%2,%3};"
        : "+f"(c[0]), "+f"(c[1]), "+f"(c[2]), "+f"(c[3])
        : "r"(a[0]), "r"(a[1]), "r"(a[2]), "r"(a[3]), "r"(b[0]), "r"(b[1]));
}

// ---------------------------------------------------------------------------
// Conv body 1: tf32 tensor-core GEMM with 3xTF32 compensation (R10, verbatim
// logic).  Uses 67584 B of dynamic smem.
// ---------------------------------------------------------------------------
#define APLANE 2112                 // 16 groups * 132 floats
#define BPLANE 2112                 // 32 groups * 66 floats
#define SLABF  (2*APLANE + 2*BPLANE)  // 8448 floats per buffer
#define CONV_SMEM (2*SLABF*4)       // 67584 bytes

__device__ __forceinline__
void conv_mma_body(float* sm, const float* __restrict__ Wm,
                   const float* __restrict__ X, float* __restrict__ F,
                   int m_base, int n_base, int t)
{
    const int w    = t >> 5;
    const int lane = t & 31;
    const int g    = lane >> 2;
    const int tg   = lane & 3;

    const int s_mt = t >> 5;
    const float* Wr1 = Wm + (size_t)(m_base + s_mt * 16 + g) * CH;
    const float* Wr2 = Wr1 + (size_t)8 * CH;
    const int aAdr0 = (0 * 8 + s_mt) * 132 + lane * 4;
    const int aAdr1 = (1 * 8 + s_mt) * 132 + lane * 4;
    const int brow  = t >> 4;
    const int bntile = t & 15;
    const float* Xp = X + (size_t)brow * PIX + n_base + bntile * 8;
    const int bhalf = brow >> 3, r8 = brow & 7;
    const int bpair = r8 >> 2,  btg = r8 & 3;
    const int bFragBase = (bhalf * 16 + bntile) * 66 + btg * 2 + bpair;

    const int wm = w >> 2;
    const int wn = w & 3;

    float acc[4][4][4];
    #pragma unroll
    for (int i = 0; i < 4; i++)
        #pragma unroll
        for (int j = 0; j < 4; j++)
            #pragma unroll
            for (int q = 0; q < 4; q++) acc[i][j][q] = 0.f;

    float  aR[2][4];
    float4 bR[2];

    auto ldSlab = [&](int k0) {
        #pragma unroll
        for (int h = 0; h < 2; h++) {
            const int kb = k0 + h * 8;
            aR[h][0] = Wr1[kb + tg];
            aR[h][1] = Wr2[kb + tg];
            aR[h][2] = Wr1[kb + tg + 4];
            aR[h][3] = Wr2[kb + tg + 4];
        }
        bR[0] = *(const float4*)(Xp + (size_t)k0 * PIX);
        bR[1] = *(const float4*)(Xp + (size_t)k0 * PIX + 4);
    };
    auto stage = [&](int buf) {
        float* base = sm + buf * SLABF;
        float* aHi = base;
        float* aLo = base + APLANE;
        float* bHi = base + 2 * APLANE;
        float* bLo = base + 2 * APLANE + BPLANE;
        #pragma unroll
        for (int h = 0; h < 2; h++) {
            float hi[4], lo[4];
            #pragma unroll
            for (int q = 0; q < 4; q++) {
                hi[q] = tf32r(aR[h][q]);
                lo[q] = tf32r(aR[h][q] - hi[q]);
            }
            const int adr = h ? aAdr1 : aAdr0;
            *(float4*)&aHi[adr] = make_float4(hi[0], hi[1], hi[2], hi[3]);
            *(float4*)&aLo[adr] = make_float4(lo[0], lo[1], lo[2], lo[3]);
        }
        float bv[8] = {bR[0].x, bR[0].y, bR[0].z, bR[0].w,
                       bR[1].x, bR[1].y, bR[1].z, bR[1].w};
        #pragma unroll
        for (int j = 0; j < 8; j++) {
            float hi = tf32r(bv[j]);
            float lo = tf32r(bv[j] - hi);
            bHi[bFragBase + j * 8] = hi;
            bLo[bFragBase + j * 8] = lo;
        }
    };
    auto compute = [&](int buf) {
        const float* base = sm + buf * SLABF;
        #pragma unroll
        for (int h = 0; h < 2; h++) {
            uint32_t aH[4][4], aL[4][4], bH[4][2], bL[4][2];
            #pragma unroll
            for (int i = 0; i < 4; i++) {
                const int adr = (h * 8 + wm * 4 + i) * 132 + lane * 4;
                *(uint4*)aH[i] = *(const uint4*)&base[adr];
                *(uint4*)aL[i] = *(const uint4*)&base[APLANE + adr];
            }
            #pragma unroll
            for (int j = 0; j < 4; j++) {
                const int adr = (h * 16 + wn * 4 + j) * 66 + lane * 2;
                *(uint2*)bH[j] = *(const uint2*)&base[2 * APLANE + adr];
                *(uint2*)bL[j] = *(const uint2*)&base[2 * APLANE + BPLANE + adr];
            }
            #pragma unroll
            for (int i = 0; i < 4; i++)
                #pragma unroll
                for (int j = 0; j < 4; j++) {
                    mma1688(acc[i][j], aH[i], bH[j]);
                    mma1688(acc[i][j], aH[i], bL[j]);
                    mma1688(acc[i][j], aL[i], bH[j]);
                }
        }
    };

    ldSlab(0);
    stage(0);
    __syncthreads();

    for (int it = 0; it < 32; ++it) {
        const int buf = it & 1;
        if (it < 31) ldSlab((it + 1) * 16);
        compute(buf);
        if (it < 31) {
            stage(buf ^ 1);
            __syncthreads();
        }
    }

    #pragma unroll
    for (int i = 0; i < 4; i++) {
        const int row0 = m_base + wm * 64 + i * 16 + g;
        #pragma unroll
        for (int j = 0; j < 4; j++) {
            const int col = n_base + wn * 32 + j * 8 + 2 * tg;
            *(float2*)&F[(size_t)row0 * PIX + col] =
                make_float2(acc[i][j][0], acc[i][j][1]);
            *(float2*)&F[(size_t)(row0 + 8) * PIX + col] =
                make_float2(acc[i][j][2], acc[i][j][3]);
        }
    }
}

// ---------------------------------------------------------------------------
// Conv body 2: exact fp32 SIMT SGEMM (R3 conv_gemm, verbatim logic, smem
// rebased into the dynamic buffer).  Uses 16 KB of the dynamic smem.
// ---------------------------------------------------------------------------
__device__ __forceinline__
void conv_ffma_body(float* sm, const float* __restrict__ Wm,
                    const float* __restrict__ X, float* __restrict__ F,
                    int m_base, int n_base, int t)
{
    float* As = sm;            // [2][8][128] -> (buf*8+k)*128 + m
    float* Bs = sm + 2048;     // [2][8][128]

    const int arow = t >> 1;
    const int acol = (t & 1) * 4;
    const int brow = t >> 5;
    const int bcol = (t & 31) * 4;

    const float* Aptr = Wm + (size_t)(m_base + arow) * CH + acol;
    const float* Bptr = X  + (size_t)brow * PIX + n_base + bcol;

    const int m0 = (t >> 4) * 8;
    const int n0 = (t & 15) * 8;

    float acc[8][8];
    #pragma unroll
    for (int i = 0; i < 8; i++)
        #pragma unroll
        for (int j = 0; j < 8; j++) acc[i][j] = 0.f;

    {
        float4 a = *(const float4*)(Aptr);
        float4 b = *(const float4*)(Bptr);
        As[(acol + 0) * 128 + arow] = a.x;
        As[(acol + 1) * 128 + arow] = a.y;
        As[(acol + 2) * 128 + arow] = a.z;
        As[(acol + 3) * 128 + arow] = a.w;
        *(float4*)&Bs[brow * 128 + bcol] = b;
    }
    __syncthreads();

    for (int kt = 0; kt < 64; ++kt) {
        const int buf = kt & 1;
        const int bo  = buf * 1024;
        float4 an, bn;
        if (kt < 63) {
            an = *(const float4*)(Aptr + (kt + 1) * 8);
            bn = *(const float4*)(Bptr + (size_t)(kt + 1) * 8 * PIX);
        }
        #pragma unroll
        for (int k = 0; k < 8; ++k) {
            float4 a0 = *(const float4*)&As[bo + k * 128 + m0];
            float4 a1 = *(const float4*)&As[bo + k * 128 + m0 + 4];
            float4 b0 = *(const float4*)&Bs[bo + k * 128 + n0];
            float4 b1 = *(const float4*)&Bs[bo + k * 128 + n0 + 4];
            float ra[8] = {a0.x, a0.y, a0.z, a0.w, a1.x, a1.y, a1.z, a1.w};
            float rb[8] = {b0.x, b0.y, b0.z, b0.w, b1.x, b1.y, b1.z, b1.w};
            #pragma unroll
            for (int i = 0; i < 8; i++)
                #pragma unroll
                for (int j = 0; j < 8; j++)
                    acc[i][j] = fmaf(ra[i], rb[j], acc[i][j]);
        }
        if (kt < 63) {
            const int no = (buf ^ 1) * 1024;
            As[no + (acol + 0) * 128 + arow] = an.x;
            As[no + (acol + 1) * 128 + arow] = an.y;
            As[no + (acol + 2) * 128 + arow] = an.z;
            As[no + (acol + 3) * 128 + arow] = an.w;
            *(float4*)&Bs[no + brow * 128 + bcol] = bn;
            __syncthreads();
        }
    }

    #pragma unroll
    for (int i = 0; i < 8; i++) {
        float* o = F + (size_t)(m_base + m0 + i) * PIX + n_base + n0;
        *(float4*)(o)     = make_float4(acc[i][0], acc[i][1], acc[i][2], acc[i][3]);
        *(float4*)(o + 4) = make_float4(acc[i][4], acc[i][5], acc[i][6], acc[i][7]);
    }
}

// ---------------------------------------------------------------------------
// Kernel A: hybrid conv — 9/16 of N-tiles on the tensor pipe (3xTF32 HMMA),
// 7/16 on the FMA pipe (exact fp32).  Co-resident CTA types overlap the two
// independent pipes on each SM.
// ---------------------------------------------------------------------------
__global__ __launch_bounds__(256, 2)
void conv_hybrid(const float* __restrict__ opt, const float* __restrict__ sar,
                 const float* __restrict__ Wopt, const float* __restrict__ Wsar)
{
    extern __shared__ float sm[];
    const int branch = blockIdx.z >> 3;
    const int batch  = blockIdx.z & 7;
    const float* __restrict__ Wm = branch ? Wsar : Wopt;
    const float* __restrict__ X  = (branch ? sar : opt) + (size_t)batch * CP;
    float* __restrict__ F = g_f[branch] + (size_t)batch * CP;
    const int m_base = blockIdx.y * 128;
    const int n_base = blockIdx.x * 128;

    if ((blockIdx.x & 15) < 9)
        conv_mma_body(sm, Wm, X, F, m_base, n_base, threadIdx.x);
    else
        conv_ffma_body(sm, Wm, X, F, m_base, n_base, threadIdx.x);
}

// ---------------------------------------------------------------------------
// Kernel B: hybrid Gram S = f^T f — even bc on tensor pipe (direct-LDG
// fragments, 3xTF32), odd bc on FMA pipe (smem SIMT, exact fp32).
// ---------------------------------------------------------------------------
__global__ __launch_bounds__(256)
void attn_hybrid()
{
    __shared__ float sh[2][4096];                // used by ffma path only
    const int bc = blockIdx.x;                   // 0..4095 = b*512+c
    const int t  = threadIdx.x;

    if ((bc & 1) == 0) {
        // ---- tensor path (R14 attn_mma body) ----
        const int w  = t >> 5, lane = t & 31;
        const int g  = lane >> 2, tg = lane & 3;
        const int br = w >> 2, m = w & 3;

        const float* __restrict__ fp = g_f[br] + (size_t)bc * PIX;

        float acc[8][4];
        #pragma unroll
        for (int j = 0; j < 8; j++)
            #pragma unroll
            for (int q = 0; q < 4; q++) acc[j][q] = 0.f;

        #pragma unroll
        for (int k = 0; k < 8; k++) {
            const float* r0 = fp + (8 * k + tg) * 64;
            const float* r4 = r0 + 4 * 64;
            float a0 = r0[16 * m + g];
            float a1 = r0[16 * m + g + 8];
            float a2 = r4[16 * m + g];
            float a3 = r4[16 * m + g + 8];
            uint32_t aH[4], aL[4];
            {
                float h0 = tf32r(a0), h1 = tf32r(a1), h2 = tf32r(a2), h3 = tf32r(a3);
                aH[0] = __float_as_uint(h0); aL[0] = __float_as_uint(tf32r(a0 - h0));
                aH[1] = __float_as_uint(h1); aL[1] = __float_as_uint(tf32r(a1 - h1));
                aH[2] = __float_as_uint(h2); aL[2] = __float_as_uint(tf32r(a2 - h2));
                aH[3] = __float_as_uint(h3); aL[3] = __float_as_uint(tf32r(a3 - h3));
            }
            #pragma unroll
            for (int j = 0; j < 8; j++) {
                float b0 = r0[8 * j + g];
                float b1 = r4[8 * j + g];
                uint32_t bH[2], bL[2];
                float h0 = tf32r(b0), h1 = tf32r(b1);
                bH[0] = __float_as_uint(h0); bL[0] = __float_as_uint(tf32r(b0 - h0));
                bH[1] = __float_as_uint(h1); bL[1] = __float_as_uint(tf32r(b1 - h1));
                mma1688(acc[j], aH, bH);
                mma1688(acc[j], aH, bL);
                mma1688(acc[j], aL, bH);
            }
        }

        float* S = g_S[br] + (size_t)bc * PIX;
        #pragma unroll
        for (int j = 0; j < 8; j++) {
            const int col = j * 8 + 2 * tg;
            *(float2*)&S[(m * 16 + g) * 64 + col]     = make_float2(acc[j][0], acc[j][1]);
            *(float2*)&S[(m * 16 + g + 8) * 64 + col] = make_float2(acc[j][2], acc[j][3]);
        }
    } else {
        // ---- FMA path: exact fp32, 256 threads (128 per branch, 8x4 tile) ----
        {
            const float4* g0 = (const float4*)(g_f[0] + (size_t)bc * PIX);
            const float4* g1 = (const float4*)(g_f[1] + (size_t)bc * PIX);
            float4* s0 = (float4*)&sh[0][0];
            float4* s1 = (float4*)&sh[1][0];
            #pragma unroll
            for (int i = 0; i < 4; i++) {
                s0[t + 256 * i] = g0[t + 256 * i];
                s1[t + 256 * i] = g1[t + 256 * i];
            }
        }
        __syncthreads();

        const int branch = t >> 7;
        const int tt = t & 127;
        const int i0 = (tt >> 4) * 8;         // 8 row-blocks of 8
        const int j0 = (tt & 15) * 4;         // 16 col-blocks of 4

        float acc[8][4];
        #pragma unroll
        for (int i = 0; i < 8; i++)
            #pragma unroll
            for (int j = 0; j < 4; j++) acc[i][j] = 0.f;

        const float* shb = &sh[branch][0];
        for (int h = 0; h < 64; ++h) {
            float4 a0 = *(const float4*)&shb[h * 64 + i0];
            float4 a1 = *(const float4*)&shb[h * 64 + i0 + 4];
            float4 b  = *(const float4*)&shb[h * 64 + j0];
            float ra[8] = {a0.x, a0.y, a0.z, a0.w, a1.x, a1.y, a1.z, a1.w};
            float rb[4] = {b.x, b.y, b.z, b.w};
            #pragma unroll
            for (int i = 0; i < 8; i++)
                #pragma unroll
                for (int j = 0; j < 4; j++)
                    acc[i][j] = fmaf(ra[i], rb[j], acc[i][j]);
        }

        float* S = g_S[branch] + (size_t)bc * PIX;
        #pragma unroll
        for (int i = 0; i < 8; i++)
            *(float4*)&S[(i0 + i) * 64 + j0] =
                make_float4(acc[i][0], acc[i][1], acc[i][2], acc[i][3]);
    }
}

// ---------------------------------------------------------------------------
// Kernel C: online softmax statistics over channel dim for both branches.
// ---------------------------------------------------------------------------
__global__ __launch_bounds__(256)
void softmax_stats()
{
    const int p = blockIdx.x * 256 + threadIdx.x;   // 0..4095
    const int b = blockIdx.y;
    const float* __restrict__ s1 = g_S[0] + (size_t)b * CP + p;
    const float* __restrict__ s2 = g_S[1] + (size_t)b * CP + p;

    float m1 = -3.4e38f, z1 = 0.f;
    float m2 = -3.4e38f, z2 = 0.f;
    #pragma unroll 8
    for (int c = 0; c < CH; ++c) {
        float v1 = s1[c * PIX];
        float v2 = s2[c * PIX];
        float nm1 = fmaxf(m1, v1);
        z1 = z1 * __expf(m1 - nm1) + __expf(v1 - nm1);
        m1 = nm1;
        float nm2 = fmaxf(m2, v2);
        z2 = z2 * __expf(m2 - nm2) + __expf(v2 - nm2);
        m2 = nm2;
    }
    g_red[b * PIX + p] = make_float4(m1, z1, m2, z2);
}

// ---------------------------------------------------------------------------
// Kernel D: Att = f1*f2 * exp(2*((s1-m1)+(s2-m2))) / (z1*z2)^2
// ---------------------------------------------------------------------------
__global__ __launch_bounds__(256)
void finalize(float* __restrict__ out)
{
    const int e = blockIdx.x * 256 + threadIdx.x;
    const int b = e >> 21;          // / (CH*PIX)
    const int p = e & (PIX - 1);
    float4 r = g_red[(b << 12) + p];
    float s1 = g_S[0][e];
    float s2 = g_S[1][e];
    float f1 = g_f[0][e];
    float f2 = g_f[1][e];
    float rz = 1.0f / (r.y * r.w);
    float ex = __expf(2.0f * ((s1 - r.x) + (s2 - r.z)));
    out[e] = (f1 * f2) * (ex * rz * rz);
}

// ---------------------------------------------------------------------------
extern "C" void kernel_launch(void* const* d_in, const int* in_sizes, int n_in,
                              void* d_out, int out_size)
{
    const float* opt  = (const float*)d_in[0];
    const float* sar  = (const float*)d_in[1];
    const float* Wopt = (const float*)d_in[2];
    const float* Wsar = (const float*)d_in[3];
    float* out = (float*)d_out;

    cudaFuncSetAttribute(conv_hybrid, cudaFuncAttributeMaxDynamicSharedMemorySize,
                         CONV_SMEM);

    conv_hybrid<<<dim3(32, 4, 16), 256, CONV_SMEM>>>(opt, sar, Wopt, Wsar);
    attn_hybrid<<<dim3(4096, 1, 1), 256>>>();
    softmax_stats<<<dim3(16, 8), 256>>>();
    finalize<<<TOT / 256, 256>>>(out);
}

// round 17
// speedup vs baseline: 1.2064x; 1.2064x over previous
#include <cuda_runtime.h>
#include <cstdint>

#define BATCH 8
#define CH    512
#define PIX   4096            // 64*64
#define CP    (CH*PIX)        // 2,097,152
#define TOT   (BATCH*CP)      // 16,777,216

// Scratch (device globals: allocation-free per harness rules)
__device__ float  g_f[2][TOT];      // conv outputs f_opt / f_sar
__device__ float  g_S[2][TOT];      // Gram matrices S_opt / S_sar
__device__ float4 g_red[BATCH*PIX]; // per-(b,pixel): (m1, z1, m2, z2)

// Pre-split fragment-major operand planes for the conv GEMM
// B (X): [bz][k8 0..63][nt 0..511][e 0..63]   e = 8*n_off + 2*tg + s,
//        value = X[c = k8*8 + tg + 4*s][n = nt*8 + n_off]        (64/group)
__device__ float g_bHi[16][64 * 512 * 64];   // 134 MB
__device__ float g_bLo[16][64 * 512 * 64];   // 134 MB
// A (W): [br][k8 0..63][mg 0..31][e 0..127]  e = 4*l + q  (128/group!),
//        q0:(row g,   k tg) q1:(row g+8, k tg) q2:(g, tg+4) q3:(g+8, tg+4)
//        with g = l>>2, tg = l&3, row_global = mg*16 + row
__device__ float g_aHi[2][64 * 32 * 128];    // 1 MB each plane
__device__ float g_aLo[2][64 * 32 * 128];

// ---------------------------------------------------------------------------
// helpers
// ---------------------------------------------------------------------------
__device__ __forceinline__ float tf32r(float x) {
    uint32_t u; asm("cvt.rna.tf32.f32 %0, %1;" : "=r"(u) : "f"(x));
    return __uint_as_float(u);
}
__device__ __forceinline__ void mma1688(float* c, const uint32_t* a, const uint32_t* b) {
    asm volatile(
        "mma.sync.aligned.m16n8k8.row.col.f32.tf32.tf32.f32 "
        "{%0,%1,%2,%3}, {%4,%5,%6,%7}, {%8,%9}, {%0,%1,%2,%3};"
        : "+f"(c[0]), "+f"(c[1]), "+f"(c[2]), "+f"(c[3])
        : "r"(a[0]), "r"(a[1]), "r"(a[2]), "r"(a[3]), "r"(b[0]), "r"(b[1]));
}
__device__ __forceinline__ void cp16(uint32_t smem, const float* g) {
    asm volatile("cp.async.cg.shared.global [%0], [%1], 16;"
                 :: "r"(smem), "l"(g) : "memory");
}
__device__ __forceinline__ void cp_commit() {
    asm volatile("cp.async.commit_group;" ::: "memory");
}
__device__ __forceinline__ void cp_wait1() {
    asm volatile("cp.async.wait_group 1;" ::: "memory");
}
__device__ __forceinline__ void cp_wait0() {
    asm volatile("cp.async.wait_group 0;" ::: "memory");
}

// ---------------------------------------------------------------------------
// Prep A: split W into tf32 hi/lo fragment-major planes (128 floats/group).
// grid (64, 2) x 256.
// ---------------------------------------------------------------------------
__global__ __launch_bounds__(256)
void prep_a(const float* __restrict__ Wopt, const float* __restrict__ Wsar)
{
    const int k8 = blockIdx.x;
    const int br = blockIdx.y;
    const float* __restrict__ W = br ? Wsar : Wopt;
    const int t = threadIdx.x;

    #pragma unroll
    for (int i = 0; i < 4; i++) {
        const int gid = t + 256 * i;          // 0..1023 = mg*32 + l
        const int mg = gid >> 5, l = gid & 31;
        const int g = l >> 2, tg = l & 3;
        const int o1 = mg * 16 + g, o2 = o1 + 8;
        const int c1 = k8 * 8 + tg, c2 = c1 + 4;
        float v0 = W[(size_t)o1 * CH + c1];
        float v1 = W[(size_t)o2 * CH + c1];
        float v2 = W[(size_t)o1 * CH + c2];
        float v3 = W[(size_t)o2 * CH + c2];
        float h0 = tf32r(v0), h1 = tf32r(v1), h2 = tf32r(v2), h3 = tf32r(v3);
        const int off = (k8 * 32 + mg) * 128 + l * 4;
        *(float4*)&g_aHi[br][off] = make_float4(h0, h1, h2, h3);
        *(float4*)&g_aLo[br][off] = make_float4(tf32r(v0 - h0), tf32r(v1 - h1),
                                                tf32r(v2 - h2), tf32r(v3 - h3));
    }
}

// ---------------------------------------------------------------------------
// Prep B: split X into tf32 hi/lo fragment-major planes.
// grid (4 n-quarters, 64 k8, 16 bz) x 256.  Smem-transposed for coalescing.
// ---------------------------------------------------------------------------
__global__ __launch_bounds__(256)
void prep_b(const float* __restrict__ opt, const float* __restrict__ sar)
{
    __shared__ float sh[8][1024];
    const int nq = blockIdx.x;          // 0..3   (1024-col quarter)
    const int k8 = blockIdx.y;          // 0..63
    const int bz = blockIdx.z;          // branch*8 + batch
    const int branch = bz >> 3, batch = bz & 7;
    const float* __restrict__ X = (branch ? sar : opt) + (size_t)batch * CP
                                + (size_t)(k8 * 8) * PIX + nq * 1024;
    const int t = threadIdx.x;

    // coalesced load 8 rows x 1024 cols
    #pragma unroll
    for (int i = 0; i < 8; i++) {
        const int id = t + 256 * i;       // row = id>>8, col4 = (id&255)*4
        const int row = id >> 8, c4 = (id & 255) * 4;
        *(float4*)&sh[row][c4] = *(const float4*)(X + (size_t)row * PIX + c4);
    }
    __syncthreads();

    float* __restrict__ oHi = g_bHi[bz] + ((size_t)k8 * 512 + nq * 128) * 64;
    float* __restrict__ oLo = g_bLo[bz] + ((size_t)k8 * 512 + nq * 128) * 64;

    #pragma unroll
    for (int i = 0; i < 8; i++) {
        const int cid = t + 256 * i;      // 0..2047 chunks of 4 floats
        const int nt_l = cid >> 4;        // 0..127
        const int e0   = (cid & 15) * 4;
        float h[4], lo[4];
        #pragma unroll
        for (int q = 0; q < 4; q++) {
            const int e = e0 + q;
            const int c_off = ((e >> 1) & 3) + 4 * (e & 1);
            const int n_off = e >> 3;
            float v = sh[c_off][nt_l * 8 + n_off];
            h[q] = tf32r(v);
            lo[q] = tf32r(v - h[q]);
        }
        const int off = nt_l * 64 + e0;
        *(float4*)&oHi[off] = make_float4(h[0], h[1], h[2], h[3]);
        *(float4*)&oLo[off] = make_float4(lo[0], lo[1], lo[2], lo[3]);
    }
}

// ---------------------------------------------------------------------------
// Kernel A: conv GEMM mainloop — pure cp.async pipeline + HMMA (3xTF32).
// CTA: 128(M) x 128(N), K slab 16 (2 k8), 3-stage pipeline, 256 threads.
// Stage layout (floats): aHi[2][8][128] | aLo | bHi[2][16][64] | bLo
//   = 2048 * 4 = 8192 floats = 32 KB; 3 stages = 96 KB.
// ---------------------------------------------------------------------------
#define STG_FL   8192
#define CONV_SMEM (3 * STG_FL * 4)     // 98304 bytes

__global__ __launch_bounds__(256, 2)
void conv_mma2()
{
    extern __shared__ float sm[];
    const uint32_t sm_u32 = (uint32_t)__cvta_generic_to_shared(sm);

    const int t    = threadIdx.x;
    const int w    = t >> 5;
    const int lane = t & 31;
    const int g    = lane >> 2;
    const int tg   = lane & 3;

    const int bz     = blockIdx.z;
    const int branch = bz >> 3, batch = bz & 7;
    float* __restrict__ F = g_f[branch] + (size_t)batch * CP;

    const int m_tile = blockIdx.y;        // 0..3
    const int n_tile = blockIdx.x;        // 0..31
    const int mg_base = m_tile * 8;
    const int nt_base = n_tile * 16;
    const int m_base  = m_tile * 128;
    const int n_base  = n_tile * 128;

    // ---- per-thread cp.async offsets (slab-invariant parts) ----
    // A chunks (2 per plane): id = 2t+u -> k8h = id>>8, mg = (id>>5)&7,
    //                         pos = (id&31)*4   (group stride 128!)
    int  aSrc[2]; uint32_t aDst[2];
    // B chunks (2 per plane): id = 2t+u -> k8h = id>>8, nt = (id>>4)&15, pos
    int  bSrc[2]; uint32_t bDst[2];
    #pragma unroll
    for (int u = 0; u < 2; u++) {
        const int id = 2 * t + u;
        const int ak8h = id >> 8, amg = (id >> 5) & 7, apos = (id & 31) * 4;
        aSrc[u] = ((ak8h * 32) + mg_base + amg) * 128 + apos;      // + s*8192
        aDst[u] = (uint32_t)((((ak8h * 8 + amg) * 128) + apos) * 4);
        const int bk8h = id >> 8, nt = (id >> 4) & 15, bpos = (id & 15) * 4;
        bSrc[u] = ((bk8h * 512) + nt_base + nt) * 64 + bpos;       // + s*65536
        bDst[u] = (uint32_t)(((bk8h * 16 + nt) * 64 + bpos) * 4);
    }
    const float* __restrict__ gAhi = g_aHi[branch];
    const float* __restrict__ gAlo = g_aLo[branch];
    const float* __restrict__ gBhi = g_bHi[bz];
    const float* __restrict__ gBlo = g_bLo[bz];

    auto issue = [&](int s, int st) {
        const uint32_t sb = sm_u32 + st * (STG_FL * 4);
        #pragma unroll
        for (int u = 0; u < 2; u++) {
            const int sa = aSrc[u] + s * 8192;
            cp16(sb + aDst[u],             gAhi + sa);
            cp16(sb + 2048 * 4 + aDst[u],  gAlo + sa);
            const int sbo = bSrc[u] + s * 65536;
            cp16(sb + 4096 * 4 + bDst[u],  gBhi + sbo);
            cp16(sb + 6144 * 4 + bDst[u],  gBlo + sbo);
        }
    };

    // ---- compute coordinates ----
    const int wm = w >> 2;            // 0..1
    const int wn = w & 3;             // 0..3

    float acc[4][4][4];
    #pragma unroll
    for (int i = 0; i < 4; i++)
        #pragma unroll
        for (int j = 0; j < 4; j++)
            #pragma unroll
            for (int q = 0; q < 4; q++) acc[i][j][q] = 0.f;

    // prologue: 2 stages in flight
    issue(0, 0); cp_commit();
    issue(1, 1); cp_commit();

    int cst = 0, ist = 2;
    for (int s = 0; s < 32; ++s) {
        if (s == 31) cp_wait0(); else cp_wait1();   // slab s complete
        __syncthreads();
        if (s + 2 < 32) {
            issue(s + 2, ist); cp_commit();
            ist = (ist == 2) ? 0 : ist + 1;
        }

        const float* base = sm + cst * STG_FL;
        cst = (cst == 2) ? 0 : cst + 1;
        #pragma unroll
        for (int h = 0; h < 2; h++) {
            uint32_t aH[4][4], aL[4][4];
            #pragma unroll
            for (int i = 0; i < 4; i++) {
                const int adr = (h * 8 + wm * 4 + i) * 128 + lane * 4;
                *(uint4*)aH[i] = *(const uint4*)&base[adr];
                *(uint4*)aL[i] = *(const uint4*)&base[2048 + adr];
            }
            #pragma unroll
            for (int j = 0; j < 4; j++) {
                const int adr = (h * 16 + wn * 4 + j) * 64 + lane * 2;
                uint32_t bH[2], bL[2];
                *(uint2*)bH = *(const uint2*)&base[4096 + adr];
                *(uint2*)bL = *(const uint2*)&base[6144 + adr];
                #pragma unroll
                for (int i = 0; i < 4; i++) {
                    mma1688(acc[i][j], aH[i], bH);
                    mma1688(acc[i][j], aH[i], bL);
                    mma1688(acc[i][j], aL[i], bH);
                }
            }
        }
    }

    // epilogue: frag (c0,c1)=row g cols 2tg..; (c2,c3)=row g+8
    #pragma unroll
    for (int i = 0; i < 4; i++) {
        const int row0 = m_base + wm * 64 + i * 16 + g;
        #pragma unroll
        for (int j = 0; j < 4; j++) {
            const int col = n_base + wn * 32 + j * 8 + 2 * tg;
            *(float2*)&F[(size_t)row0 * PIX + col] =
                make_float2(acc[i][j][0], acc[i][j][1]);
            *(float2*)&F[(size_t)(row0 + 8) * PIX + col] =
                make_float2(acc[i][j][2], acc[i][j][3]);
        }
    }
}

// ---------------------------------------------------------------------------
// Kernel B: per-(b,c) Gram matrix S = f^T f (R3 FFMA version — known good).
// ---------------------------------------------------------------------------
__global__ __launch_bounds__(128)
void attn_gemm()
{
    const int bc = blockIdx.x;                   // 0..4095 = b*512+c
    __shared__ float sh[2][64][64];

    const int t = threadIdx.x;
    {
        const float4* g0 = (const float4*)(g_f[0] + (size_t)bc * PIX);
        const float4* g1 = (const float4*)(g_f[1] + (size_t)bc * PIX);
        float4* s0 = (float4*)&sh[0][0][0];
        float4* s1 = (float4*)&sh[1][0][0];
        #pragma unroll
        for (int i = 0; i < 8; i++) {
            s0[t + 128 * i] = g0[t + 128 * i];
            s1[t + 128 * i] = g1[t + 128 * i];
        }
    }
    __syncthreads();

    const int branch = t >> 6;
    const int tt = t & 63;
    const int i0 = (tt >> 3) * 8;
    const int j0 = (tt & 7) * 8;

    float acc[8][8];
    #pragma unroll
    for (int i = 0; i < 8; i++)
        #pragma unroll
        for (int j = 0; j < 8; j++) acc[i][j] = 0.f;

    for (int h = 0; h < 64; ++h) {
        float4 a0 = *(const float4*)&sh[branch][h][i0];
        float4 a1 = *(const float4*)&sh[branch][h][i0 + 4];
        float4 b0 = *(const float4*)&sh[branch][h][j0];
        float4 b1 = *(const float4*)&sh[branch][h][j0 + 4];
        float ra[8] = {a0.x, a0.y, a0.z, a0.w, a1.x, a1.y, a1.z, a1.w};
        float rb[8] = {b0.x, b0.y, b0.z, b0.w, b1.x, b1.y, b1.z, b1.w};
        #pragma unroll
        for (int i = 0; i < 8; i++)
            #pragma unroll
            for (int j = 0; j < 8; j++)
                acc[i][j] = fmaf(ra[i], rb[j], acc[i][j]);
    }

    float* S = g_S[branch] + (size_t)bc * PIX;
    #pragma unroll
    for (int i = 0; i < 8; i++) {
        float* o = S + (i0 + i) * 64 + j0;
        *(float4*)(o)     = make_float4(acc[i][0], acc[i][1], acc[i][2], acc[i][3]);
        *(float4*)(o + 4) = make_float4(acc[i][4], acc[i][5], acc[i][6], acc[i][7]);
    }
}

// ---------------------------------------------------------------------------
// Kernel C: online softmax statistics over channel dim for both branches.
// ---------------------------------------------------------------------------
__global__ __launch_bounds__(256)
void softmax_stats()
{
    const int p = blockIdx.x * 256 + threadIdx.x;   // 0..4095
    const int b = blockIdx.y;
    const float* __restrict__ s1 = g_S[0] + (size_t)b * CP + p;
    const float* __restrict__ s2 = g_S[1] + (size_t)b * CP + p;

    float m1 = -3.4e38f, z1 = 0.f;
    float m2 = -3.4e38f, z2 = 0.f;
    #pragma unroll 8
    for (int c = 0; c < CH; ++c) {
        float v1 = s1[c * PIX];
        float v2 = s2[c * PIX];
        float nm1 = fmaxf(m1, v1);
        z1 = z1 * __expf(m1 - nm1) + __expf(v1 - nm1);
        m1 = nm1;
        float nm2 = fmaxf(m2, v2);
        z2 = z2 * __expf(m2 - nm2) + __expf(v2 - nm2);
        m2 = nm2;
    }
    g_red[b * PIX + p] = make_float4(m1, z1, m2, z2);
}

// ---------------------------------------------------------------------------
// Kernel D: Att = f1*f2 * exp(2*((s1-m1)+(s2-m2))) / (z1*z2)^2
// ---------------------------------------------------------------------------
__global__ __launch_bounds__(256)
void finalize(float* __restrict__ out)
{
    const int e = blockIdx.x * 256 + threadIdx.x;
    const int b = e >> 21;          // / (CH*PIX)
    const int p = e & (PIX - 1);
    float4 r = g_red[(b << 12) + p];
    float s1 = g_S[0][e];
    float s2 = g_S[1][e];
    float f1 = g_f[0][e];
    float f2 = g_f[1][e];
    float rz = 1.0f / (r.y * r.w);
    float ex = __expf(2.0f * ((s1 - r.x) + (s2 - r.z)));
    out[e] = (f1 * f2) * (ex * rz * rz);
}

// ---------------------------------------------------------------------------
extern "C" void kernel_launch(void* const* d_in, const int* in_sizes, int n_in,
                              void* d_out, int out_size)
{
    const float* opt  = (const float*)d_in[0];
    const float* sar  = (const float*)d_in[1];
    const float* Wopt = (const float*)d_in[2];
    const float* Wsar = (const float*)d_in[3];
    float* out = (float*)d_out;

    cudaFuncSetAttribute(conv_mma2, cudaFuncAttributeMaxDynamicSharedMemorySize,
                         CONV_SMEM);

    prep_a<<<dim3(64, 2), 256>>>(Wopt, Wsar);
    prep_b<<<dim3(4, 64, 16), 256>>>(opt, sar);
    conv_mma2<<<dim3(32, 4, 16), 256, CONV_SMEM>>>();
    attn_gemm<<<dim3(4096, 1, 1), 128>>>();
    softmax_stats<<<dim3(16, 8), 256>>>();
    finalize<<<TOT / 256, 256>>>(out);
}